// round 8
// baseline (speedup 1.0000x reference)
#include <cuda_runtime.h>
#include <cstdint>

// ---------------- problem constants ----------------
#define T_TOK   8192
#define DMODEL  1024
#define DFF     4096
#define NEXP    8
#define ECAP    4096                 // fixed capacity per expert
#define NSLOTS  (NEXP * ECAP)        // 32768
#define MAXTILES 160

// ---------------- device scratch (static; no allocation) ----------------
__device__ float g_h[(size_t)NSLOTS * DFF];            // 512 MiB (raw fp32)
__device__ float g_y[(size_t)NSLOTS * DMODEL];         // 128 MiB
__device__ int   g_tok[NSLOTS];
__device__ int   g_s0[T_TOK], g_s1[T_TOK];
__device__ float g_w0[T_TOK], g_w1w[T_TOK];
__device__ int   g_fill[NEXP];
__device__ int   g_ntiles;
__device__ int   g_tile_e[MAXTILES], g_tile_start[MAXTILES], g_tile_cnt[MAXTILES];

// ---------------- helpers ----------------
__device__ __forceinline__ float tf32r(float x) {
    uint32_t u;
    asm("cvt.rna.tf32.f32 %0, %1;" : "=r"(u) : "f"(x));
    return __uint_as_float(u);
}
__device__ __forceinline__ uint32_t smem_u32(const void* p) {
    uint32_t a;
    asm("{ .reg .u64 t; cvta.to.shared.u64 t, %1; cvt.u32.u64 %0, t; }" : "=r"(a) : "l"(p));
    return a;
}
__device__ __forceinline__ void cp16(uint32_t dst, const void* src) {
    asm volatile("cp.async.cg.shared.global [%0], [%1], 16;" :: "r"(dst), "l"(src));
}
__device__ __forceinline__ void cp_commit() {
    asm volatile("cp.async.commit_group;" ::: "memory");
}
__device__ __forceinline__ void cp_wait1() {
    asm volatile("cp.async.wait_group 1;" ::: "memory");
}
// LDS + round-to-tf32 (RNA) in one helper: operand fed to HMMA is always RNA-rounded
__device__ __forceinline__ uint32_t ldsr(uint32_t addr) {
    float v;
    asm volatile("ld.shared.f32 %0, [%1];" : "=f"(v) : "r"(addr));
    uint32_t u;
    asm("cvt.rna.tf32.f32 %0, %1;" : "=r"(u) : "f"(v));
    return u;
}
__device__ __forceinline__ void mma_tf32(float* d, const uint32_t* a, const uint32_t* b) {
    asm volatile(
        "mma.sync.aligned.m16n8k8.row.col.f32.tf32.tf32.f32 "
        "{%0,%1,%2,%3}, {%4,%5,%6,%7}, {%8,%9}, {%0,%1,%2,%3};\n"
        : "+f"(d[0]), "+f"(d[1]), "+f"(d[2]), "+f"(d[3])
        : "r"(a[0]), "r"(a[1]), "r"(a[2]), "r"(a[3]),
          "r"(b[0]), "r"(b[1]));
}

// ---------------- launch 0: zero expert fill counters ----------------
__global__ void init_kernel() {
    if (threadIdx.x < NEXP) g_fill[threadIdx.x] = 0;
}

// ---------------- launch 1: gate + direct slot assignment ----------------
__global__ void gate_kernel(const float* __restrict__ x, const float* __restrict__ gumbel,
                            const float* __restrict__ gw, const float* __restrict__ gb) {
    int t = (blockIdx.x * blockDim.x + threadIdx.x) >> 5;
    int lane = threadIdx.x & 31;
    if (t >= T_TOK) return;
    const float* xr = x + (size_t)t * DMODEL;
    float acc[NEXP];
#pragma unroll
    for (int e = 0; e < NEXP; e++) acc[e] = 0.f;
    for (int d = lane * 4; d < DMODEL; d += 128) {
        float4 xv = *reinterpret_cast<const float4*>(xr + d);
        float xs[4] = {xv.x, xv.y, xv.z, xv.w};
        const float* g0 = gw + (size_t)d * NEXP;
#pragma unroll
        for (int j = 0; j < 4; j++)
#pragma unroll
            for (int e = 0; e < NEXP; e++) acc[e] += xs[j] * g0[j * NEXP + e];
    }
#pragma unroll
    for (int e = 0; e < NEXP; e++)
#pragma unroll
        for (int off = 16; off; off >>= 1)
            acc[e] += __shfl_xor_sync(0xffffffffu, acc[e], off);
    if (lane == 0) {
        float v[NEXP];
#pragma unroll
        for (int e = 0; e < NEXP; e++) v[e] = acc[e] + gb[e] + gumbel[t * NEXP + e];
        int b0 = 0; float m0 = v[0];
#pragma unroll
        for (int e = 1; e < NEXP; e++) if (v[e] > m0) { m0 = v[e]; b0 = e; }
        int b1 = -1; float m1 = -3.4e38f;
#pragma unroll
        for (int e = 0; e < NEXP; e++) {
            if (e == b0) continue;
            if (v[e] > m1) { m1 = v[e]; b1 = e; }
        }
        float e1v = expf(m1 - m0);
        float inv = 1.f / (1.f + e1v);
        g_w0[t] = inv; g_w1w[t] = e1v * inv;
        int s0 = b0 * ECAP + atomicAdd(&g_fill[b0], 1);
        g_tok[s0] = t; g_s0[t] = s0;
        int s1 = b1 * ECAP + atomicAdd(&g_fill[b1], 1);
        g_tok[s1] = t; g_s1[t] = s1;
    }
}

// ---------------- launch 2: build m-tile map ----------------
__global__ void tilemap_kernel() {
    if (threadIdx.x == 0) {
        int nt = 0;
        for (int e = 0; e < NEXP; e++) {
            int c = g_fill[e];
            if (c > ECAP) c = ECAP;
            int base = e * ECAP;
            for (int s = 0; s < c; s += 128) {
                g_tile_e[nt] = e;
                g_tile_start[nt] = base + s;
                g_tile_cnt[nt] = (c - s < 128) ? (c - s) : 128;
                nt++;
            }
        }
        g_ntiles = nt;
    }
}

// ---------------- grouped GEMM: BM=128 BN=128 BK=32, 4 warps, warp tile 64x64 ----
// cp.async 3-stage, swizzled smem. RNA-to-tf32 applied in-register at fragment
// load (ldsr) -> no weight/x pre-rounding pass needed (saves 512MB+32MB traffic).
#define STAGE_BYTES 32768
#define NSTAGE 3
#define SM_TOKS (NSTAGE * STAGE_BYTES)          // 98304
#define SMEM_TOT (SM_TOKS + 512)

template <bool GATHER, bool RELU>
__global__ void __launch_bounds__(128, 2)
gemm_cp(const float* __restrict__ Aext, int lda,
        const float* __restrict__ B, long estride, int ldb,
        const float* __restrict__ bias, int ldo, int Ksize) {
    extern __shared__ char smem[];
    int bx = blockIdx.x;
    if (bx >= g_ntiles) return;
    int e = g_tile_e[bx];
    int slot0 = g_tile_start[bx];
    int mc = g_tile_cnt[bx];
    int n0 = blockIdx.y * 128;

    uint32_t sm = smem_u32(smem);
    int tid = threadIdx.x;
    int lane = tid & 31, wid = tid >> 5;
    int wm = wid >> 1, wn = wid & 1;          // 2x2 warps, 64x64 each
    int gid = lane >> 2, tig = lane & 3;

    const float* Abase = GATHER ? Aext : g_h;
    const float* biasE = bias + (size_t)e * ldo;

    int* toks = reinterpret_cast<int*>(smem + SM_TOKS);
    if (GATHER) {
        if (tid < 128) {
            int r = tid < mc ? tid : (mc - 1);
            toks[tid] = g_tok[slot0 + r];
        }
        __syncthreads();
    }

    // ---- staging constants (per thread: 8 x 16B for A, 8 x 16B for B) ----
    int r0 = tid >> 3, kg = tid & 7;
    uint32_t aD0 = (uint32_t)r0 * 128u + 16u * (uint32_t)(kg ^ (r0 & 7));
    int bk0 = tid >> 5, bcg = tid & 31;
    uint32_t bD0 = (uint32_t)bk0 * 512u + 16u * (uint32_t)(bcg ^ (2 * (bk0 & 3)));

    uint32_t arow[8];
#pragma unroll
    for (int i = 0; i < 8; i++) {
        int row = i * 16 + r0;
        int rr = GATHER ? toks[row] : (slot0 + row);
        arow[i] = (uint32_t)rr * (uint32_t)lda;
    }
    const float* Ab = Abase + kg * 4;
    const float* Bp = B + (size_t)e * estride + (size_t)bk0 * ldb + n0 + bcg * 4;

    // ---- fragment addressing ----
    uint32_t arel = (uint32_t)(wm * 64 + gid) * 128u + (uint32_t)tig * 4u;
    uint32_t aoffv[8];
#pragma unroll
    for (int u = 0; u < 8; u++) aoffv[u] = 16u * (uint32_t)(u ^ gid);
    uint32_t brel[8];
#pragma unroll
    for (int nt = 0; nt < 8; nt++) {
        uint32_t cg = (uint32_t)(wn * 16 + nt * 2 + (gid >> 2));
        brel[nt] = (uint32_t)tig * 512u + 16u * (cg ^ (uint32_t)(2 * tig)) + (uint32_t)(gid & 3) * 4u;
    }

    float c[4][8][4];
#pragma unroll
    for (int mt = 0; mt < 4; mt++)
#pragma unroll
        for (int nt = 0; nt < 8; nt++)
#pragma unroll
            for (int q = 0; q < 4; q++) c[mt][nt][q] = 0.f;

    const int nk = Ksize / 32;

    // prologue: stages 0 and 1
#pragma unroll
    for (int s = 0; s < 2; s++) {
        uint32_t sb = sm + (uint32_t)s * STAGE_BYTES;
#pragma unroll
        for (int i = 0; i < 8; i++) cp16(sb + aD0 + (uint32_t)i * 2048u, Ab + arow[i] + s * 32);
#pragma unroll
        for (int i = 0; i < 8; i++) cp16(sb + 16384u + bD0 + (uint32_t)i * 2048u,
                                         Bp + (size_t)(s * 32 + i * 4) * ldb);
        cp_commit();
    }

    int stage = 0;
    for (int kc = 0; kc < nk; kc++) {
        cp_wait1();
        __syncthreads();
        if (kc + 2 < nk) {
            int s2 = stage + 2; if (s2 >= NSTAGE) s2 -= NSTAGE;
            uint32_t sb = sm + (uint32_t)s2 * STAGE_BYTES;
            int ko = (kc + 2) * 32;
#pragma unroll
            for (int i = 0; i < 8; i++) cp16(sb + aD0 + (uint32_t)i * 2048u, Ab + arow[i] + ko);
#pragma unroll
            for (int i = 0; i < 8; i++) cp16(sb + 16384u + bD0 + (uint32_t)i * 2048u,
                                             Bp + (size_t)(ko + i * 4) * ldb);
        }
        cp_commit();

        uint32_t aB = sm + (uint32_t)stage * STAGE_BYTES;
        uint32_t bB = aB + 16384u;
#pragma unroll
        for (int ks = 0; ks < 4; ks++) {
            uint32_t af[4][4];
#pragma unroll
            for (int mt = 0; mt < 4; mt++) {
                uint32_t base = aB + arel + (uint32_t)(mt * 2048);
                uint32_t a0 = base + aoffv[2 * ks];
                uint32_t a2 = base + aoffv[2 * ks + 1];
                af[mt][0] = ldsr(a0);
                af[mt][1] = ldsr(a0 + 1024u);
                af[mt][2] = ldsr(a2);
                af[mt][3] = ldsr(a2 + 1024u);
            }
            uint32_t bf[8][2];
#pragma unroll
            for (int nt = 0; nt < 8; nt++) {
                uint32_t b0 = bB + brel[nt] + (uint32_t)(ks * 4096);
                bf[nt][0] = ldsr(b0);
                bf[nt][1] = ldsr(b0 + 2048u);
            }
#pragma unroll
            for (int mt = 0; mt < 4; mt++)
#pragma unroll
                for (int nt = 0; nt < 8; nt++)
                    mma_tf32(c[mt][nt], af[mt], bf[nt]);
        }
        stage++; if (stage >= NSTAGE) stage -= NSTAGE;
    }

    // ---- epilogue: +bias (, relu); store raw fp32 (rounding happens at next load) ----
    float* Out = RELU ? g_h : g_y;
#pragma unroll
    for (int mt = 0; mt < 4; mt++) {
#pragma unroll
        for (int half = 0; half < 2; half++) {
            int r = wm * 64 + mt * 16 + gid + half * 8;
            if (r < mc) {
                float* orow = Out + (size_t)(slot0 + r) * ldo;
#pragma unroll
                for (int nt = 0; nt < 8; nt++) {
                    int nc = n0 + wn * 64 + nt * 8 + 2 * tig;
                    float v0 = c[mt][nt][half * 2 + 0] + biasE[nc];
                    float v1 = c[mt][nt][half * 2 + 1] + biasE[nc + 1];
                    if (RELU) { v0 = fmaxf(v0, 0.f); v1 = fmaxf(v1, 0.f); }
                    orow[nc]     = v0;
                    orow[nc + 1] = v1;
                }
            }
        }
    }
}

// ---------------- combine ----------------
__global__ void combine_kernel(float* __restrict__ out) {
    int idx = blockIdx.x * blockDim.x + threadIdx.x;
    if (idx >= T_TOK * (DMODEL / 4)) return;
    int t = idx / (DMODEL / 4);
    int j = (idx % (DMODEL / 4)) * 4;
    float w0 = g_w0[t], w1 = g_w1w[t];
    const float4 a = *reinterpret_cast<const float4*>(&g_y[(size_t)g_s0[t] * DMODEL + j]);
    const float4 b = *reinterpret_cast<const float4*>(&g_y[(size_t)g_s1[t] * DMODEL + j]);
    float4 o;
    o.x = w0 * a.x + w1 * b.x;
    o.y = w0 * a.y + w1 * b.y;
    o.z = w0 * a.z + w1 * b.z;
    o.w = w0 * a.w + w1 * b.w;
    *reinterpret_cast<float4*>(out + (size_t)t * DMODEL + j) = o;
}

// ---------------- launch (ncu captures launch index 3 = GEMM1) ----------------
extern "C" void kernel_launch(void* const* d_in, const int* in_sizes, int n_in,
                              void* d_out, int out_size) {
    const float* x      = (const float*)d_in[0];
    const float* gumbel = (const float*)d_in[1];
    const float* gw     = (const float*)d_in[2];
    const float* gb     = (const float*)d_in[3];
    const float* w1     = (const float*)d_in[4];
    const float* b1     = (const float*)d_in[5];
    const float* w2     = (const float*)d_in[6];
    const float* b2     = (const float*)d_in[7];
    float* out = (float*)d_out;

    cudaFuncSetAttribute(gemm_cp<true, true>,
                         cudaFuncAttributeMaxDynamicSharedMemorySize, SMEM_TOT);
    cudaFuncSetAttribute(gemm_cp<false, false>,
                         cudaFuncAttributeMaxDynamicSharedMemorySize, SMEM_TOT);

    // 0: counter zeroing
    init_kernel<<<1, 32>>>();
    // 1: gate (logits, top-2, slot assignment)
    gate_kernel<<<T_TOK * 32 / 256, 256>>>(x, gumbel, gw, gb);
    // 2: tile map
    tilemap_kernel<<<1, 32>>>();
    // 3: GEMM1  h = relu(x[tok] @ w1[e] + b1[e])   K=DMODEL, N=DFF  (RNA in-reg)
    gemm_cp<true, true><<<dim3(MAXTILES, DFF / 128), 128, SMEM_TOT>>>(
        x, DMODEL, w1, (long)DMODEL * DFF, DFF, b1, DFF, DMODEL);
    // 4: GEMM2  y = h @ w2[e] + b2[e]              K=DFF, N=DMODEL  (RNA in-reg)
    gemm_cp<false, false><<<dim3(MAXTILES, DMODEL / 128), 128, SMEM_TOT>>>(
        nullptr, DFF, w2, (long)DFF * DMODEL, DMODEL, b2, DMODEL, DFF);
    // 5: combine
    combine_kernel<<<(T_TOK * (DMODEL / 4) + 255) / 256, 256>>>(out);
}

// round 10
// speedup vs baseline: 1.0402x; 1.0402x over previous
#include <cuda_runtime.h>
#include <cstdint>

// ---------------- problem constants ----------------
#define T_TOK   8192
#define DMODEL  1024
#define DFF     4096
#define NEXP    8
#define ECAP    4096                 // fixed capacity per expert
#define NSLOTS  (NEXP * ECAP)        // 32768
#define MAXTILES 160

// ---------------- device scratch (static; no allocation) ----------------
__device__ float g_h[(size_t)NSLOTS * DFF];            // 512 MiB (tf32-rounded fp32)
__device__ float g_y[(size_t)NSLOTS * DMODEL];         // 128 MiB
__device__ float g_w1r[(size_t)NEXP * DMODEL * DFF];   // RNA-rounded w1
__device__ float g_w2r[(size_t)NEXP * DFF * DMODEL];   // RNA-rounded w2
__device__ float g_xr[(size_t)T_TOK * DMODEL];         // RNA-rounded x
__device__ int   g_tok[NSLOTS];
__device__ int   g_s0[T_TOK], g_s1[T_TOK];
__device__ float g_w0[T_TOK], g_w1w[T_TOK];
__device__ int   g_fill[NEXP];
__device__ int   g_ntiles;
__device__ int   g_tile_e[MAXTILES], g_tile_start[MAXTILES], g_tile_cnt[MAXTILES];

// ---------------- helpers ----------------
__device__ __forceinline__ float tf32r(float x) {
    uint32_t u;
    asm("cvt.rna.tf32.f32 %0, %1;" : "=r"(u) : "f"(x));
    return __uint_as_float(u);
}
__device__ __forceinline__ uint32_t smem_u32(const void* p) {
    uint32_t a;
    asm("{ .reg .u64 t; cvta.to.shared.u64 t, %1; cvt.u32.u64 %0, t; }" : "=r"(a) : "l"(p));
    return a;
}
__device__ __forceinline__ void cp16(uint32_t dst, const void* src) {
    asm volatile("cp.async.cg.shared.global [%0], [%1], 16;" :: "r"(dst), "l"(src));
}
__device__ __forceinline__ void cp_commit() {
    asm volatile("cp.async.commit_group;" ::: "memory");
}
__device__ __forceinline__ void cp_wait1() {
    asm volatile("cp.async.wait_group 1;" ::: "memory");
}
__device__ __forceinline__ float lds(uint32_t addr) {
    float v;
    asm volatile("ld.shared.f32 %0, [%1];" : "=f"(v) : "r"(addr));
    return v;
}
__device__ __forceinline__ void mma_tf32(float* d, const uint32_t* a, const uint32_t* b) {
    asm volatile(
        "mma.sync.aligned.m16n8k8.row.col.f32.tf32.tf32.f32 "
        "{%0,%1,%2,%3}, {%4,%5,%6,%7}, {%8,%9}, {%0,%1,%2,%3};\n"
        : "+f"(d[0]), "+f"(d[1]), "+f"(d[2]), "+f"(d[3])
        : "r"(a[0]), "r"(a[1]), "r"(a[2]), "r"(a[3]),
          "r"(b[0]), "r"(b[1]));
}

// ---------------- launch 0: RNA-round both weight tensors (+ zero fill counters) ----
#define W_ELEMS4 ((size_t)NEXP * DMODEL * DFF / 4)
__global__ void rna_weights(const float* __restrict__ w1, const float* __restrict__ w2) {
    if (blockIdx.x == 0 && threadIdx.x < NEXP) g_fill[threadIdx.x] = 0;
    size_t i = (size_t)blockIdx.x * blockDim.x + threadIdx.x;
    if (i < W_ELEMS4) {
        float4 v = reinterpret_cast<const float4*>(w1)[i];
        v.x = tf32r(v.x); v.y = tf32r(v.y); v.z = tf32r(v.z); v.w = tf32r(v.w);
        reinterpret_cast<float4*>(g_w1r)[i] = v;
    } else if (i < 2 * W_ELEMS4) {
        size_t j = i - W_ELEMS4;
        float4 v = reinterpret_cast<const float4*>(w2)[j];
        v.x = tf32r(v.x); v.y = tf32r(v.y); v.z = tf32r(v.z); v.w = tf32r(v.w);
        reinterpret_cast<float4*>(g_w2r)[j] = v;
    }
}

// ---------------- launch 1: gate + RNA(x) + direct slot assignment ----------------
__global__ void gate_kernel(const float* __restrict__ x, const float* __restrict__ gumbel,
                            const float* __restrict__ gw, const float* __restrict__ gb) {
    int t = (blockIdx.x * blockDim.x + threadIdx.x) >> 5;
    int lane = threadIdx.x & 31;
    if (t >= T_TOK) return;
    const float* xr = x + (size_t)t * DMODEL;
    float* xo = g_xr + (size_t)t * DMODEL;
    float acc[NEXP];
#pragma unroll
    for (int e = 0; e < NEXP; e++) acc[e] = 0.f;
    for (int d = lane * 4; d < DMODEL; d += 128) {
        float4 xv = *reinterpret_cast<const float4*>(xr + d);
        float4 rv;
        rv.x = tf32r(xv.x); rv.y = tf32r(xv.y); rv.z = tf32r(xv.z); rv.w = tf32r(xv.w);
        *reinterpret_cast<float4*>(xo + d) = rv;
        float xs[4] = {xv.x, xv.y, xv.z, xv.w};
        const float* g0 = gw + (size_t)d * NEXP;
#pragma unroll
        for (int j = 0; j < 4; j++)
#pragma unroll
            for (int e = 0; e < NEXP; e++) acc[e] += xs[j] * g0[j * NEXP + e];
    }
#pragma unroll
    for (int e = 0; e < NEXP; e++)
#pragma unroll
        for (int off = 16; off; off >>= 1)
            acc[e] += __shfl_xor_sync(0xffffffffu, acc[e], off);
    if (lane == 0) {
        float v[NEXP];
#pragma unroll
        for (int e = 0; e < NEXP; e++) v[e] = acc[e] + gb[e] + gumbel[t * NEXP + e];
        int b0 = 0; float m0 = v[0];
#pragma unroll
        for (int e = 1; e < NEXP; e++) if (v[e] > m0) { m0 = v[e]; b0 = e; }
        int b1 = -1; float m1 = -3.4e38f;
#pragma unroll
        for (int e = 0; e < NEXP; e++) {
            if (e == b0) continue;
            if (v[e] > m1) { m1 = v[e]; b1 = e; }
        }
        float e1v = expf(m1 - m0);
        float inv = 1.f / (1.f + e1v);
        g_w0[t] = inv; g_w1w[t] = e1v * inv;
        int s0 = b0 * ECAP + atomicAdd(&g_fill[b0], 1);
        g_tok[s0] = t; g_s0[t] = s0;
        int s1 = b1 * ECAP + atomicAdd(&g_fill[b1], 1);
        g_tok[s1] = t; g_s1[t] = s1;
    }
}

// ---------------- launch 2: build m-tile map ----------------
__global__ void tilemap_kernel() {
    if (threadIdx.x == 0) {
        int nt = 0;
        for (int e = 0; e < NEXP; e++) {
            int c = g_fill[e];
            if (c > ECAP) c = ECAP;
            int base = e * ECAP;
            for (int s = 0; s < c; s += 128) {
                g_tile_e[nt] = e;
                g_tile_start[nt] = base + s;
                g_tile_cnt[nt] = (c - s < 128) ? (c - s) : 128;
                nt++;
            }
        }
        g_ntiles = nt;
    }
}

// ---------------- grouped GEMM: BM=128 BN=128 BK=32, 4 warps, warp tile 64x64 ----
// cp.async 3-stage, swizzled smem. GRID: blockIdx.x = n-tile (FASTEST),
// blockIdx.y = m-tile. A wave holds all n-strips of one m-tile -> the A slab is
// fetched from DRAM once and L2-hit by siblings (kills GEMM2's 8x re-stream of
// the 512MB g_h).
#define STAGE_BYTES 32768
#define NSTAGE 3
#define SM_TOKS (NSTAGE * STAGE_BYTES)          // 98304
#define SMEM_TOT (SM_TOKS + 512)

template <bool GATHER, bool RELU>
__global__ void __launch_bounds__(128, 2)
gemm_cp(const float* __restrict__ Aext, int lda,
        const float* __restrict__ B, long estride, int ldb,
        const float* __restrict__ bias, int ldo, int Ksize) {
    extern __shared__ char smem[];
    int tix = blockIdx.y;                     // m-tile (slow axis)
    if (tix >= g_ntiles) return;
    int e = g_tile_e[tix];
    int slot0 = g_tile_start[tix];
    int mc = g_tile_cnt[tix];
    int n0 = blockIdx.x * 128;                // n-tile (fast axis)

    uint32_t sm = smem_u32(smem);
    int tid = threadIdx.x;
    int lane = tid & 31, wid = tid >> 5;
    int wm = wid >> 1, wn = wid & 1;          // 2x2 warps, 64x64 each
    int gid = lane >> 2, tig = lane & 3;

    const float* Abase = GATHER ? Aext : g_h;
    const float* biasE = bias + (size_t)e * ldo;

    int* toks = reinterpret_cast<int*>(smem + SM_TOKS);
    if (GATHER) {
        if (tid < 128) {
            int r = tid < mc ? tid : (mc - 1);
            toks[tid] = g_tok[slot0 + r];
        }
        __syncthreads();
    }

    // ---- staging constants (per thread: 8 x 16B for A, 8 x 16B for B) ----
    int r0 = tid >> 3, kg = tid & 7;
    uint32_t aD0 = (uint32_t)r0 * 128u + 16u * (uint32_t)(kg ^ (r0 & 7));
    int bk0 = tid >> 5, bcg = tid & 31;
    uint32_t bD0 = (uint32_t)bk0 * 512u + 16u * (uint32_t)(bcg ^ (2 * (bk0 & 3)));

    uint32_t arow[8];
#pragma unroll
    for (int i = 0; i < 8; i++) {
        int row = i * 16 + r0;
        int rr = GATHER ? toks[row] : (slot0 + row);
        arow[i] = (uint32_t)rr * (uint32_t)lda;
    }
    const float* Ab = Abase + kg * 4;
    const float* Bp = B + (size_t)e * estride + (size_t)bk0 * ldb + n0 + bcg * 4;

    // ---- fragment addressing ----
    uint32_t arel = (uint32_t)(wm * 64 + gid) * 128u + (uint32_t)tig * 4u;
    uint32_t aoffv[8];
#pragma unroll
    for (int u = 0; u < 8; u++) aoffv[u] = 16u * (uint32_t)(u ^ gid);
    uint32_t brel[8];
#pragma unroll
    for (int nt = 0; nt < 8; nt++) {
        uint32_t cg = (uint32_t)(wn * 16 + nt * 2 + (gid >> 2));
        brel[nt] = (uint32_t)tig * 512u + 16u * (cg ^ (uint32_t)(2 * tig)) + (uint32_t)(gid & 3) * 4u;
    }

    float c[4][8][4];
#pragma unroll
    for (int mt = 0; mt < 4; mt++)
#pragma unroll
        for (int nt = 0; nt < 8; nt++)
#pragma unroll
            for (int q = 0; q < 4; q++) c[mt][nt][q] = 0.f;

    const int nk = Ksize / 32;

    // prologue: stages 0 and 1
#pragma unroll
    for (int s = 0; s < 2; s++) {
        uint32_t sb = sm + (uint32_t)s * STAGE_BYTES;
#pragma unroll
        for (int i = 0; i < 8; i++) cp16(sb + aD0 + (uint32_t)i * 2048u, Ab + arow[i] + s * 32);
#pragma unroll
        for (int i = 0; i < 8; i++) cp16(sb + 16384u + bD0 + (uint32_t)i * 2048u,
                                         Bp + (size_t)(s * 32 + i * 4) * ldb);
        cp_commit();
    }

    int stage = 0;
    for (int kc = 0; kc < nk; kc++) {
        cp_wait1();
        __syncthreads();
        if (kc + 2 < nk) {
            int s2 = stage + 2; if (s2 >= NSTAGE) s2 -= NSTAGE;
            uint32_t sb = sm + (uint32_t)s2 * STAGE_BYTES;
            int ko = (kc + 2) * 32;
#pragma unroll
            for (int i = 0; i < 8; i++) cp16(sb + aD0 + (uint32_t)i * 2048u, Ab + arow[i] + ko);
#pragma unroll
            for (int i = 0; i < 8; i++) cp16(sb + 16384u + bD0 + (uint32_t)i * 2048u,
                                             Bp + (size_t)(ko + i * 4) * ldb);
        }
        cp_commit();

        uint32_t aB = sm + (uint32_t)stage * STAGE_BYTES;
        uint32_t bB = aB + 16384u;
#pragma unroll
        for (int ks = 0; ks < 4; ks++) {
            uint32_t af[4][4];
#pragma unroll
            for (int mt = 0; mt < 4; mt++) {
                uint32_t base = aB + arel + (uint32_t)(mt * 2048);
                uint32_t a0 = base + aoffv[2 * ks];
                uint32_t a2 = base + aoffv[2 * ks + 1];
                af[mt][0] = __float_as_uint(lds(a0));
                af[mt][1] = __float_as_uint(lds(a0 + 1024u));
                af[mt][2] = __float_as_uint(lds(a2));
                af[mt][3] = __float_as_uint(lds(a2 + 1024u));
            }
            uint32_t bf[8][2];
#pragma unroll
            for (int nt = 0; nt < 8; nt++) {
                uint32_t b0 = bB + brel[nt] + (uint32_t)(ks * 4096);
                bf[nt][0] = __float_as_uint(lds(b0));
                bf[nt][1] = __float_as_uint(lds(b0 + 2048u));
            }
#pragma unroll
            for (int mt = 0; mt < 4; mt++)
#pragma unroll
                for (int nt = 0; nt < 8; nt++)
                    mma_tf32(c[mt][nt], af[mt], bf[nt]);
        }
        stage++; if (stage >= NSTAGE) stage -= NSTAGE;
    }

    // ---- epilogue: +bias (, relu + RNA) ----
    float* Out = RELU ? g_h : g_y;
#pragma unroll
    for (int mt = 0; mt < 4; mt++) {
#pragma unroll
        for (int half = 0; half < 2; half++) {
            int r = wm * 64 + mt * 16 + gid + half * 8;
            if (r < mc) {
                float* orow = Out + (size_t)(slot0 + r) * ldo;
#pragma unroll
                for (int nt = 0; nt < 8; nt++) {
                    int nc = n0 + wn * 64 + nt * 8 + 2 * tig;
                    float v0 = c[mt][nt][half * 2 + 0] + biasE[nc];
                    float v1 = c[mt][nt][half * 2 + 1] + biasE[nc + 1];
                    if (RELU) {
                        v0 = tf32r(fmaxf(v0, 0.f));
                        v1 = tf32r(fmaxf(v1, 0.f));
                    }
                    orow[nc]     = v0;
                    orow[nc + 1] = v1;
                }
            }
        }
    }
}

// ---------------- combine ----------------
__global__ void combine_kernel(float* __restrict__ out) {
    int idx = blockIdx.x * blockDim.x + threadIdx.x;
    if (idx >= T_TOK * (DMODEL / 4)) return;
    int t = idx / (DMODEL / 4);
    int j = (idx % (DMODEL / 4)) * 4;
    float w0 = g_w0[t], w1 = g_w1w[t];
    const float4 a = *reinterpret_cast<const float4*>(&g_y[(size_t)g_s0[t] * DMODEL + j]);
    const float4 b = *reinterpret_cast<const float4*>(&g_y[(size_t)g_s1[t] * DMODEL + j]);
    float4 o;
    o.x = w0 * a.x + w1 * b.x;
    o.y = w0 * a.y + w1 * b.y;
    o.z = w0 * a.z + w1 * b.z;
    o.w = w0 * a.w + w1 * b.w;
    *reinterpret_cast<float4*>(out + (size_t)t * DMODEL + j) = o;
}

// ---------------- launch (ncu captures GEMM1 at same launch index as R7) ----------
extern "C" void kernel_launch(void* const* d_in, const int* in_sizes, int n_in,
                              void* d_out, int out_size) {
    const float* x      = (const float*)d_in[0];
    const float* gumbel = (const float*)d_in[1];
    const float* gw     = (const float*)d_in[2];
    const float* gb     = (const float*)d_in[3];
    const float* w1     = (const float*)d_in[4];
    const float* b1     = (const float*)d_in[5];
    const float* w2     = (const float*)d_in[6];
    const float* b2     = (const float*)d_in[7];
    float* out = (float*)d_out;

    cudaFuncSetAttribute(gemm_cp<true, true>,
                         cudaFuncAttributeMaxDynamicSharedMemorySize, SMEM_TOT);
    cudaFuncSetAttribute(gemm_cp<false, false>,
                         cudaFuncAttributeMaxDynamicSharedMemorySize, SMEM_TOT);

    float* xr;  cudaGetSymbolAddress((void**)&xr,  g_xr);
    float* w1r; cudaGetSymbolAddress((void**)&w1r, g_w1r);
    float* w2r; cudaGetSymbolAddress((void**)&w2r, g_w2r);

    // 0: weight RNA + counter zeroing
    size_t n4 = 2 * W_ELEMS4;
    rna_weights<<<(unsigned)((n4 + 255) / 256), 256>>>(w1, w2);
    // 1: gate (logits, top-2, slot assignment, RNA(x))
    gate_kernel<<<T_TOK * 32 / 256, 256>>>(x, gumbel, gw, gb);
    // 2: tile map
    tilemap_kernel<<<1, 32>>>();
    // 3: GEMM1  h = rna(relu(xr[tok] @ w1r[e] + b1[e]))   K=DMODEL, N=DFF
    //    grid: x = n-tiles (fast), y = m-tiles (slow)
    gemm_cp<true, true><<<dim3(DFF / 128, MAXTILES), 128, SMEM_TOT>>>(
        xr, DMODEL, w1r, (long)DMODEL * DFF, DFF, b1, DFF, DMODEL);
    // 4: GEMM2  y = h @ w2r[e] + b2[e]                    K=DFF, N=DMODEL
    gemm_cp<false, false><<<dim3(DMODEL / 128, MAXTILES), 128, SMEM_TOT>>>(
        nullptr, DFF, w2r, (long)DFF * DMODEL, DMODEL, b2, DMODEL, DFF);
    // 5: combine
    combine_kernel<<<(T_TOK * (DMODEL / 4) + 255) / 256, 256>>>(out);
}

// round 11
// speedup vs baseline: 1.6321x; 1.5690x over previous
#include <cuda_runtime.h>
#include <cuda_fp16.h>
#include <cstdint>

// ---------------- problem constants ----------------
#define T_TOK   8192
#define DMODEL  1024
#define DFF     4096
#define NEXP    8
#define ECAP    4096
#define NSLOTS  (NEXP * ECAP)                  // 32768
#define MAXTILES 160

// ---------------- device scratch (static; no allocation) ----------------
__device__ __align__(16) __half    g_hh[(size_t)NSLOTS * DFF];        // 256 MiB h (fp16)
__device__ __align__(16) float     g_y[(size_t)NSLOTS * DMODEL];      // 128 MiB
__device__ __align__(16) __half    g_xh[(size_t)T_TOK * DMODEL];      // 16 MiB
// packed half2 weights: [e][kp][n], uint = (half lo = k=2kp, half hi = k=2kp+1)
__device__ __align__(16) unsigned  g_w1h[(size_t)NEXP * (DMODEL / 2) * DFF];  // 64 MiB
__device__ __align__(16) unsigned  g_w2h[(size_t)NEXP * (DFF / 2) * DMODEL];  // 64 MiB
__device__ int   g_tok[NSLOTS];
__device__ int   g_s0[T_TOK], g_s1[T_TOK];
__device__ float g_w0[T_TOK], g_w1w[T_TOK];
__device__ int   g_fill[NEXP];
__device__ int   g_ntiles;
__device__ int   g_tile_e[MAXTILES], g_tile_start[MAXTILES], g_tile_cnt[MAXTILES];

// ---------------- helpers ----------------
__device__ __forceinline__ uint32_t smem_u32(const void* p) {
    uint32_t a;
    asm("{ .reg .u64 t; cvta.to.shared.u64 t, %1; cvt.u32.u64 %0, t; }" : "=r"(a) : "l"(p));
    return a;
}
__device__ __forceinline__ void cp16(uint32_t dst, const void* src) {
    asm volatile("cp.async.cg.shared.global [%0], [%1], 16;" :: "r"(dst), "l"(src));
}
__device__ __forceinline__ void cp_commit() {
    asm volatile("cp.async.commit_group;" ::: "memory");
}
__device__ __forceinline__ void cp_wait1() {
    asm volatile("cp.async.wait_group 1;" ::: "memory");
}
__device__ __forceinline__ uint32_t ldsu(uint32_t addr) {
    uint32_t v;
    asm volatile("ld.shared.b32 %0, [%1];" : "=r"(v) : "r"(addr));
    return v;
}
__device__ __forceinline__ unsigned pack2(float lo, float hi) {
    __half2 h = __floats2half2_rn(lo, hi);
    return *reinterpret_cast<unsigned*>(&h);
}
__device__ __forceinline__ void mma_f16(float* d, const uint32_t* a, const uint32_t* b) {
    asm volatile(
        "mma.sync.aligned.m16n8k16.row.col.f32.f16.f16.f32 "
        "{%0,%1,%2,%3}, {%4,%5,%6,%7}, {%8,%9}, {%0,%1,%2,%3};\n"
        : "+f"(d[0]), "+f"(d[1]), "+f"(d[2]), "+f"(d[3])
        : "r"(a[0]), "r"(a[1]), "r"(a[2]), "r"(a[3]),
          "r"(b[0]), "r"(b[1]));
}

// ---- launch 0: convert w1/w2 -> k-pair-interleaved half2 (+ zero counters) ----
#define W_UINTS ((size_t)NEXP * (DMODEL / 2) * DFF)   // uints per weight tensor (both equal)
__global__ void convert_w(const float* __restrict__ w1, const float* __restrict__ w2) {
    if (blockIdx.x == 0 && threadIdx.x < NEXP) g_fill[threadIdx.x] = 0;
    size_t i = (size_t)blockIdx.x * blockDim.x + threadIdx.x;
    if (i < W_UINTS) {
        // w1: [e][k][n], K=DMODEL, N=DFF. out row kp -> ks 2kp,2kp+1
        size_t row = i / DFF, n = i % DFF;       // row = e*(K/2)+kp
        size_t e = row / (DMODEL / 2), kp = row % (DMODEL / 2);
        size_t base = (e * DMODEL + 2 * kp) * DFF + n;
        g_w1h[i] = pack2(w1[base], w1[base + DFF]);
    } else if (i < 2 * W_UINTS) {
        size_t j = i - W_UINTS;
        size_t row = j / DMODEL, n = j % DMODEL; // K=DFF, N=DMODEL
        size_t e = row / (DFF / 2), kp = row % (DFF / 2);
        size_t base = (e * DFF + 2 * kp) * DMODEL + n;
        g_w2h[j] = pack2(w2[base], w2[base + DMODEL]);
    }
}

// ---- launch 1: gate + fp16(x) + direct slot assignment ----
__global__ void gate_kernel(const float* __restrict__ x, const float* __restrict__ gumbel,
                            const float* __restrict__ gw, const float* __restrict__ gb) {
    int t = (blockIdx.x * blockDim.x + threadIdx.x) >> 5;
    int lane = threadIdx.x & 31;
    if (t >= T_TOK) return;
    const float* xr = x + (size_t)t * DMODEL;
    unsigned* xo = reinterpret_cast<unsigned*>(g_xh + (size_t)t * DMODEL);
    float acc[NEXP];
#pragma unroll
    for (int e = 0; e < NEXP; e++) acc[e] = 0.f;
    for (int d = lane * 4; d < DMODEL; d += 128) {
        float4 xv = *reinterpret_cast<const float4*>(xr + d);
        uint2 hv;
        hv.x = pack2(xv.x, xv.y);
        hv.y = pack2(xv.z, xv.w);
        *reinterpret_cast<uint2*>(xo + d / 2) = hv;
        float xs[4] = {xv.x, xv.y, xv.z, xv.w};
        const float* g0 = gw + (size_t)d * NEXP;
#pragma unroll
        for (int j = 0; j < 4; j++)
#pragma unroll
            for (int e = 0; e < NEXP; e++) acc[e] += xs[j] * g0[j * NEXP + e];
    }
#pragma unroll
    for (int e = 0; e < NEXP; e++)
#pragma unroll
        for (int off = 16; off; off >>= 1)
            acc[e] += __shfl_xor_sync(0xffffffffu, acc[e], off);
    if (lane == 0) {
        float v[NEXP];
#pragma unroll
        for (int e = 0; e < NEXP; e++) v[e] = acc[e] + gb[e] + gumbel[t * NEXP + e];
        int b0 = 0; float m0 = v[0];
#pragma unroll
        for (int e = 1; e < NEXP; e++) if (v[e] > m0) { m0 = v[e]; b0 = e; }
        int b1 = -1; float m1 = -3.4e38f;
#pragma unroll
        for (int e = 0; e < NEXP; e++) {
            if (e == b0) continue;
            if (v[e] > m1) { m1 = v[e]; b1 = e; }
        }
        float e1v = expf(m1 - m0);
        float inv = 1.f / (1.f + e1v);
        g_w0[t] = inv; g_w1w[t] = e1v * inv;
        int s0 = b0 * ECAP + atomicAdd(&g_fill[b0], 1);
        g_tok[s0] = t; g_s0[t] = s0;
        int s1 = b1 * ECAP + atomicAdd(&g_fill[b1], 1);
        g_tok[s1] = t; g_s1[t] = s1;
    }
}

// ---- launch 2: build m-tile map ----
__global__ void tilemap_kernel() {
    if (threadIdx.x == 0) {
        int nt = 0;
        for (int e = 0; e < NEXP; e++) {
            int c = g_fill[e];
            if (c > ECAP) c = ECAP;
            int base = e * ECAP;
            for (int s = 0; s < c; s += 128) {
                g_tile_e[nt] = e;
                g_tile_start[nt] = base + s;
                g_tile_cnt[nt] = (c - s < 128) ? (c - s) : 128;
                nt++;
            }
        }
        g_ntiles = nt;
    }
}

// ---------------- grouped GEMM, fp16 m16n8k16 ----------------
// BM=128 BN=128 BK=64(half), 4 warps (warp tile 64x64), cp.async 3-stage.
// A stage: 128 rows x 128B (64 halves), unit swizzle g^(r&7)  -> conflict-free.
// B stage: 32 kp-rows x 544B (128 half2 + 32B pad)            -> conflict-free.
#define SM_A_BYTES 16384
#define SM_B_STRIDE 544
#define STAGE_BYTES (SM_A_BYTES + 32 * SM_B_STRIDE)   // 33792
#define NSTAGE 3
#define SM_TOKS (NSTAGE * STAGE_BYTES)                 // 101376
#define SMEM_TOT (SM_TOKS + 512)

template <bool GATHER, bool RELU>
__global__ void __launch_bounds__(128, 2)
gemm_fp16(const __half* __restrict__ Aext, int lda,
          const unsigned* __restrict__ B, long estrideU, int N,
          const float* __restrict__ bias, int Ksize) {
    extern __shared__ char smem[];
    int tix = blockIdx.y;
    if (tix >= g_ntiles) return;
    int e = g_tile_e[tix];
    int slot0 = g_tile_start[tix];
    int mc = g_tile_cnt[tix];
    int n0 = blockIdx.x * 128;

    uint32_t sm = smem_u32(smem);
    int tid = threadIdx.x;
    int lane = tid & 31, wid = tid >> 5;
    int wm = wid >> 1, wn = wid & 1;
    int gid = lane >> 2, tig = lane & 3;

    const __half* Abase = GATHER ? Aext : g_hh;
    const float* biasE = bias + (size_t)e * N;

    int* toks = reinterpret_cast<int*>(smem + SM_TOKS);
    if (GATHER) {
        if (tid < 128) {
            int r = tid < mc ? tid : (mc - 1);
            toks[tid] = g_tok[slot0 + r];
        }
        __syncthreads();
    }

    // ---- A staging map: thread covers rows r0+16i, unit kg ----
    int r0 = tid >> 3, kg = tid & 7;
    uint32_t aD0 = (uint32_t)r0 * 128u + 16u * (uint32_t)(kg ^ (r0 & 7));
    uint32_t arow[8];
#pragma unroll
    for (int i = 0; i < 8; i++) {
        int row = i * 16 + r0;
        int rr = GATHER ? toks[row] : (slot0 + row);
        arow[i] = (uint32_t)rr * (uint32_t)lda;   // in halves
    }
    const __half* Ab = Abase + kg * 8;            // 8 halves per 16B unit

    // ---- B staging map: thread covers kp rows 4i+(tid>>5), unit ucol ----
    int kpL = tid >> 5, ucol = tid & 31;
    uint32_t bD0 = (uint32_t)kpL * SM_B_STRIDE + (uint32_t)ucol * 16u;
    const unsigned* Brow = B + (size_t)e * estrideU + (size_t)kpL * N + n0 + ucol * 4;

    // ---- fragment addressing ----
    uint32_t arel = (uint32_t)(wm * 64 + gid) * 128u + (uint32_t)tig * 4u;
    uint32_t aoffv[8];
#pragma unroll
    for (int u = 0; u < 8; u++) aoffv[u] = 16u * (uint32_t)(u ^ gid);
    uint32_t brel[8];
#pragma unroll
    for (int nt = 0; nt < 8; nt++)
        brel[nt] = (uint32_t)tig * SM_B_STRIDE +
                   (uint32_t)(wn * 64 + nt * 8 + gid) * 4u;

    float c[4][8][4];
#pragma unroll
    for (int mt = 0; mt < 4; mt++)
#pragma unroll
        for (int nt = 0; nt < 8; nt++)
#pragma unroll
            for (int q = 0; q < 4; q++) c[mt][nt][q] = 0.f;

    const int nk = Ksize / 64;

    // prologue: stages 0, 1
#pragma unroll
    for (int s = 0; s < 2; s++) {
        uint32_t sb = sm + (uint32_t)s * STAGE_BYTES;
#pragma unroll
        for (int i = 0; i < 8; i++)
            cp16(sb + aD0 + (uint32_t)i * 2048u, Ab + arow[i] + s * 64);
#pragma unroll
        for (int i = 0; i < 8; i++)
            cp16(sb + SM_A_BYTES + bD0 + (uint32_t)i * (4u * SM_B_STRIDE),
                 Brow + (size_t)(s * 32 + 4 * i) * N);
        cp_commit();
    }

    int stage = 0;
    for (int kc = 0; kc < nk; kc++) {
        cp_wait1();
        __syncthreads();
        if (kc + 2 < nk) {
            int s2 = stage + 2; if (s2 >= NSTAGE) s2 -= NSTAGE;
            uint32_t sb = sm + (uint32_t)s2 * STAGE_BYTES;
            int ko = (kc + 2) * 64;
#pragma unroll
            for (int i = 0; i < 8; i++)
                cp16(sb + aD0 + (uint32_t)i * 2048u, Ab + arow[i] + ko);
#pragma unroll
            for (int i = 0; i < 8; i++)
                cp16(sb + SM_A_BYTES + bD0 + (uint32_t)i * (4u * SM_B_STRIDE),
                     Brow + (size_t)((kc + 2) * 32 + 4 * i) * N);
        }
        cp_commit();

        uint32_t aB = sm + (uint32_t)stage * STAGE_BYTES;
        uint32_t bB = aB + SM_A_BYTES;
#pragma unroll
        for (int ks = 0; ks < 4; ks++) {
            uint32_t af[4][4];
#pragma unroll
            for (int mt = 0; mt < 4; mt++) {
                uint32_t base = aB + arel + (uint32_t)(mt * 2048);
                uint32_t a0 = base + aoffv[2 * ks];      // row gid,   k-lo
                uint32_t a2 = base + aoffv[2 * ks + 1];  // row gid,   k-hi
                af[mt][0] = ldsu(a0);
                af[mt][1] = ldsu(a0 + 1024u);            // row gid+8, k-lo
                af[mt][2] = ldsu(a2);
                af[mt][3] = ldsu(a2 + 1024u);            // row gid+8, k-hi
            }
            uint32_t bf[8][2];
#pragma unroll
            for (int nt = 0; nt < 8; nt++) {
                uint32_t b0 = bB + brel[nt] + (uint32_t)(ks * 8 * SM_B_STRIDE);
                bf[nt][0] = ldsu(b0);                            // kp = 8ks+tig
                bf[nt][1] = ldsu(b0 + 4u * SM_B_STRIDE);         // kp = 8ks+tig+4
            }
#pragma unroll
            for (int mt = 0; mt < 4; mt++)
#pragma unroll
                for (int nt = 0; nt < 8; nt++)
                    mma_f16(c[mt][nt], af[mt], bf[nt]);
        }
        stage++; if (stage >= NSTAGE) stage -= NSTAGE;
    }

    // ---- epilogue: +bias (, relu); RELU path stores fp16 h, else fp32 y ----
#pragma unroll
    for (int mt = 0; mt < 4; mt++) {
#pragma unroll
        for (int half = 0; half < 2; half++) {
            int r = wm * 64 + mt * 16 + gid + half * 8;
            if (r < mc) {
#pragma unroll
                for (int nt = 0; nt < 8; nt++) {
                    int nc = n0 + wn * 64 + nt * 8 + 2 * tig;
                    float v0 = c[mt][nt][half * 2 + 0] + biasE[nc];
                    float v1 = c[mt][nt][half * 2 + 1] + biasE[nc + 1];
                    if (RELU) {
                        v0 = fmaxf(v0, 0.f); v1 = fmaxf(v1, 0.f);
                        unsigned* orow = reinterpret_cast<unsigned*>(
                            g_hh + (size_t)(slot0 + r) * N);
                        orow[nc / 2] = pack2(v0, v1);
                    } else {
                        float* orow = g_y + (size_t)(slot0 + r) * N;
                        orow[nc]     = v0;
                        orow[nc + 1] = v1;
                    }
                }
            }
        }
    }
}

// ---------------- combine ----------------
__global__ void combine_kernel(float* __restrict__ out) {
    int idx = blockIdx.x * blockDim.x + threadIdx.x;
    if (idx >= T_TOK * (DMODEL / 4)) return;
    int t = idx / (DMODEL / 4);
    int j = (idx % (DMODEL / 4)) * 4;
    float w0 = g_w0[t], w1 = g_w1w[t];
    const float4 a = *reinterpret_cast<const float4*>(&g_y[(size_t)g_s0[t] * DMODEL + j]);
    const float4 b = *reinterpret_cast<const float4*>(&g_y[(size_t)g_s1[t] * DMODEL + j]);
    float4 o;
    o.x = w0 * a.x + w1 * b.x;
    o.y = w0 * a.y + w1 * b.y;
    o.z = w0 * a.z + w1 * b.z;
    o.w = w0 * a.w + w1 * b.w;
    *reinterpret_cast<float4*>(out + (size_t)t * DMODEL + j) = o;
}

// ---------------- launch (index 3 = GEMM1 for ncu) ----------------
extern "C" void kernel_launch(void* const* d_in, const int* in_sizes, int n_in,
                              void* d_out, int out_size) {
    const float* x      = (const float*)d_in[0];
    const float* gumbel = (const float*)d_in[1];
    const float* gw     = (const float*)d_in[2];
    const float* gb     = (const float*)d_in[3];
    const float* w1     = (const float*)d_in[4];
    const float* b1     = (const float*)d_in[5];
    const float* w2     = (const float*)d_in[6];
    const float* b2     = (const float*)d_in[7];
    float* out = (float*)d_out;

    cudaFuncSetAttribute(gemm_fp16<true, true>,
                         cudaFuncAttributeMaxDynamicSharedMemorySize, SMEM_TOT);
    cudaFuncSetAttribute(gemm_fp16<false, false>,
                         cudaFuncAttributeMaxDynamicSharedMemorySize, SMEM_TOT);

    __half* xh;  cudaGetSymbolAddress((void**)&xh,  g_xh);
    unsigned* w1h; cudaGetSymbolAddress((void**)&w1h, g_w1h);
    unsigned* w2h; cudaGetSymbolAddress((void**)&w2h, g_w2h);

    // 0: weight conversion to packed half2 (+ counter zeroing)
    size_t nU = 2 * W_UINTS;
    convert_w<<<(unsigned)((nU + 255) / 256), 256>>>(w1, w2);
    // 1: gate (logits, top-2, slot assignment, fp16(x))
    gate_kernel<<<T_TOK * 32 / 256, 256>>>(x, gumbel, gw, gb);
    // 2: tile map
    tilemap_kernel<<<1, 32>>>();
    // 3: GEMM1  h = fp16(relu(xh[tok] @ w1[e] + b1[e]))   K=DMODEL, N=DFF
    gemm_fp16<true, true><<<dim3(DFF / 128, MAXTILES), 128, SMEM_TOT>>>(
        xh, DMODEL, w1h, (long)(DMODEL / 2) * DFF, DFF, b1, DMODEL);
    // 4: GEMM2  y = hh @ w2[e] + b2[e]                    K=DFF, N=DMODEL
    gemm_fp16<false, false><<<dim3(DMODEL / 128, MAXTILES), 128, SMEM_TOT>>>(
        nullptr, DFF, w2h, (long)(DFF / 2) * DMODEL, DMODEL, b2, DFF);
    // 5: combine
    combine_kernel<<<(T_TOK * (DMODEL / 4) + 255) / 256, 256>>>(out);
}

// round 12
// speedup vs baseline: 1.6867x; 1.0335x over previous
#include <cuda_runtime.h>
#include <cuda_fp16.h>
#include <cstdint>

// ---------------- problem constants ----------------
#define T_TOK   8192
#define DMODEL  1024
#define DFF     4096
#define NEXP    8
#define ECAP    4096
#define NSLOTS  (NEXP * ECAP)                  // 32768
#define MAXTILES 160

// ---------------- device scratch (static; no allocation) ----------------
__device__ __align__(16) __half    g_hh[(size_t)NSLOTS * DFF];        // 256 MiB h (fp16)
__device__ __align__(16) float     g_y[(size_t)NSLOTS * DMODEL];      // 128 MiB
__device__ __align__(16) __half    g_xh[(size_t)T_TOK * DMODEL];      // 16 MiB
// packed half2 weights: [e][kp][n], uint = (half lo = k=2kp, half hi = k=2kp+1)
__device__ __align__(16) unsigned  g_w1h[(size_t)NEXP * (DMODEL / 2) * DFF];  // 64 MiB
__device__ __align__(16) unsigned  g_w2h[(size_t)NEXP * (DFF / 2) * DMODEL];  // 64 MiB
__device__ int   g_tok[NSLOTS];
__device__ int   g_s0[T_TOK], g_s1[T_TOK];
__device__ float g_w0[T_TOK], g_w1w[T_TOK];
__device__ int   g_fill[NEXP];
__device__ int   g_ntiles;
__device__ int   g_tile_e[MAXTILES], g_tile_start[MAXTILES], g_tile_cnt[MAXTILES];

// ---------------- helpers ----------------
__device__ __forceinline__ uint32_t smem_u32(const void* p) {
    uint32_t a;
    asm("{ .reg .u64 t; cvta.to.shared.u64 t, %1; cvt.u32.u64 %0, t; }" : "=r"(a) : "l"(p));
    return a;
}
__device__ __forceinline__ void cp16(uint32_t dst, const void* src) {
    asm volatile("cp.async.cg.shared.global [%0], [%1], 16;" :: "r"(dst), "l"(src));
}
__device__ __forceinline__ void cp_commit() {
    asm volatile("cp.async.commit_group;" ::: "memory");
}
__device__ __forceinline__ void cp_wait1() {
    asm volatile("cp.async.wait_group 1;" ::: "memory");
}
__device__ __forceinline__ uint32_t ldsu(uint32_t addr) {
    uint32_t v;
    asm volatile("ld.shared.b32 %0, [%1];" : "=r"(v) : "r"(addr));
    return v;
}
// A-fragment load: one ldmatrix.x4 = full 16x16 fp16 A fragment (4 regs)
__device__ __forceinline__ void ldm4(uint32_t addr, uint32_t* r) {
    asm volatile("ldmatrix.sync.aligned.m8n8.x4.shared.b16 {%0,%1,%2,%3}, [%4];"
        : "=r"(r[0]), "=r"(r[1]), "=r"(r[2]), "=r"(r[3]) : "r"(addr));
}
__device__ __forceinline__ unsigned pack2(float lo, float hi) {
    __half2 h = __floats2half2_rn(lo, hi);
    return *reinterpret_cast<unsigned*>(&h);
}
__device__ __forceinline__ void mma_f16(float* d, const uint32_t* a, const uint32_t* b) {
    asm volatile(
        "mma.sync.aligned.m16n8k16.row.col.f32.f16.f16.f32 "
        "{%0,%1,%2,%3}, {%4,%5,%6,%7}, {%8,%9}, {%0,%1,%2,%3};\n"
        : "+f"(d[0]), "+f"(d[1]), "+f"(d[2]), "+f"(d[3])
        : "r"(a[0]), "r"(a[1]), "r"(a[2]), "r"(a[3]),
          "r"(b[0]), "r"(b[1]));
}

// ---- launch 0: convert w1/w2 -> k-pair-interleaved half2 (+ zero counters) ----
#define W_UINTS ((size_t)NEXP * (DMODEL / 2) * DFF)
__global__ void convert_w(const float* __restrict__ w1, const float* __restrict__ w2) {
    if (blockIdx.x == 0 && threadIdx.x < NEXP) g_fill[threadIdx.x] = 0;
    size_t i = (size_t)blockIdx.x * blockDim.x + threadIdx.x;
    if (i < W_UINTS) {
        size_t row = i / DFF, n = i % DFF;
        size_t e = row / (DMODEL / 2), kp = row % (DMODEL / 2);
        size_t base = (e * DMODEL + 2 * kp) * DFF + n;
        g_w1h[i] = pack2(w1[base], w1[base + DFF]);
    } else if (i < 2 * W_UINTS) {
        size_t j = i - W_UINTS;
        size_t row = j / DMODEL, n = j % DMODEL;
        size_t e = row / (DFF / 2), kp = row % (DFF / 2);
        size_t base = (e * DFF + 2 * kp) * DMODEL + n;
        g_w2h[j] = pack2(w2[base], w2[base + DMODEL]);
    }
}

// ---- launch 1: gate + fp16(x) + direct slot assignment ----
__global__ void gate_kernel(const float* __restrict__ x, const float* __restrict__ gumbel,
                            const float* __restrict__ gw, const float* __restrict__ gb) {
    int t = (blockIdx.x * blockDim.x + threadIdx.x) >> 5;
    int lane = threadIdx.x & 31;
    if (t >= T_TOK) return;
    const float* xr = x + (size_t)t * DMODEL;
    unsigned* xo = reinterpret_cast<unsigned*>(g_xh + (size_t)t * DMODEL);
    float acc[NEXP];
#pragma unroll
    for (int e = 0; e < NEXP; e++) acc[e] = 0.f;
    for (int d = lane * 4; d < DMODEL; d += 128) {
        float4 xv = *reinterpret_cast<const float4*>(xr + d);
        uint2 hv;
        hv.x = pack2(xv.x, xv.y);
        hv.y = pack2(xv.z, xv.w);
        *reinterpret_cast<uint2*>(xo + d / 2) = hv;
        float xs[4] = {xv.x, xv.y, xv.z, xv.w};
        const float* g0 = gw + (size_t)d * NEXP;
#pragma unroll
        for (int j = 0; j < 4; j++)
#pragma unroll
            for (int e = 0; e < NEXP; e++) acc[e] += xs[j] * g0[j * NEXP + e];
    }
#pragma unroll
    for (int e = 0; e < NEXP; e++)
#pragma unroll
        for (int off = 16; off; off >>= 1)
            acc[e] += __shfl_xor_sync(0xffffffffu, acc[e], off);
    if (lane == 0) {
        float v[NEXP];
#pragma unroll
        for (int e = 0; e < NEXP; e++) v[e] = acc[e] + gb[e] + gumbel[t * NEXP + e];
        int b0 = 0; float m0 = v[0];
#pragma unroll
        for (int e = 1; e < NEXP; e++) if (v[e] > m0) { m0 = v[e]; b0 = e; }
        int b1 = -1; float m1 = -3.4e38f;
#pragma unroll
        for (int e = 0; e < NEXP; e++) {
            if (e == b0) continue;
            if (v[e] > m1) { m1 = v[e]; b1 = e; }
        }
        float e1v = expf(m1 - m0);
        float inv = 1.f / (1.f + e1v);
        g_w0[t] = inv; g_w1w[t] = e1v * inv;
        int s0 = b0 * ECAP + atomicAdd(&g_fill[b0], 1);
        g_tok[s0] = t; g_s0[t] = s0;
        int s1 = b1 * ECAP + atomicAdd(&g_fill[b1], 1);
        g_tok[s1] = t; g_s1[t] = s1;
    }
}

// ---- launch 2: build m-tile map ----
__global__ void tilemap_kernel() {
    if (threadIdx.x == 0) {
        int nt = 0;
        for (int e = 0; e < NEXP; e++) {
            int c = g_fill[e];
            if (c > ECAP) c = ECAP;
            int base = e * ECAP;
            for (int s = 0; s < c; s += 128) {
                g_tile_e[nt] = e;
                g_tile_start[nt] = base + s;
                g_tile_cnt[nt] = (c - s < 128) ? (c - s) : 128;
                nt++;
            }
        }
        g_ntiles = nt;
    }
}

// ---------------- grouped GEMM, fp16 m16n8k16, ldmatrix A fragments ----------------
// BM=128 BN=128 BK=64(half), 4 warps (warp tile 64x64), cp.async 3-stage.
// A stage: 128 rows x 128B, unit swizzle g^(r&7)  -> conflict-free (ldmatrix too).
// B stage: 32 kp-rows x 544B                       -> conflict-free scalar LDS.
#define SM_A_BYTES 16384
#define SM_B_STRIDE 544
#define STAGE_BYTES (SM_A_BYTES + 32 * SM_B_STRIDE)   // 33792
#define NSTAGE 3
#define SM_TOKS (NSTAGE * STAGE_BYTES)                 // 101376
#define SMEM_TOT (SM_TOKS + 512)

template <bool GATHER, bool RELU>
__global__ void __launch_bounds__(128, 2)
gemm_fp16(const __half* __restrict__ Aext, int lda,
          const unsigned* __restrict__ B, long estrideU, int N,
          const float* __restrict__ bias, int Ksize) {
    extern __shared__ char smem[];
    int tix = blockIdx.y;
    if (tix >= g_ntiles) return;
    int e = g_tile_e[tix];
    int slot0 = g_tile_start[tix];
    int mc = g_tile_cnt[tix];
    int n0 = blockIdx.x * 128;

    uint32_t sm = smem_u32(smem);
    int tid = threadIdx.x;
    int lane = tid & 31, wid = tid >> 5;
    int wm = wid >> 1, wn = wid & 1;
    int gid = lane >> 2, tig = lane & 3;

    const __half* Abase = GATHER ? Aext : g_hh;
    const float* biasE = bias + (size_t)e * N;

    int* toks = reinterpret_cast<int*>(smem + SM_TOKS);
    if (GATHER) {
        if (tid < 128) {
            int r = tid < mc ? tid : (mc - 1);
            toks[tid] = g_tok[slot0 + r];
        }
        __syncthreads();
    }

    // ---- A staging map ----
    int r0 = tid >> 3, kg = tid & 7;
    uint32_t aD0 = (uint32_t)r0 * 128u + 16u * (uint32_t)(kg ^ (r0 & 7));
    uint32_t arow[8];
#pragma unroll
    for (int i = 0; i < 8; i++) {
        int row = i * 16 + r0;
        int rr = GATHER ? toks[row] : (slot0 + row);
        arow[i] = (uint32_t)rr * (uint32_t)lda;   // in halves
    }
    const __half* Ab = Abase + kg * 8;

    // ---- B staging map ----
    int kpL = tid >> 5, ucol = tid & 31;
    uint32_t bD0 = (uint32_t)kpL * SM_B_STRIDE + (uint32_t)ucol * 16u;
    const unsigned* Brow = B + (size_t)e * estrideU + (size_t)kpL * N + n0 + ucol * 4;

    // ---- A fragment addressing (ldmatrix per-lane rows) ----
    // lanes 0-7: rows 0-7 k-lo | 8-15: rows 8-15 k-lo | 16-23: rows 0-7 k-hi | 24-31: rows 8-15 k-hi
    int rowLane = (lane & 7) + ((lane >> 3) & 1) * 8;
    int khalf = lane >> 4;
    uint32_t aRelL = (uint32_t)(wm * 64 + rowLane) * 128u;
    uint32_t uoffL[4];
#pragma unroll
    for (int ks = 0; ks < 4; ks++)
        uoffL[ks] = 16u * (uint32_t)((2 * ks + khalf) ^ (rowLane & 7));

    // ---- B fragment addressing ----
    uint32_t brel[8];
#pragma unroll
    for (int nt = 0; nt < 8; nt++)
        brel[nt] = (uint32_t)tig * SM_B_STRIDE +
                   (uint32_t)(wn * 64 + nt * 8 + gid) * 4u;

    float c[4][8][4];
#pragma unroll
    for (int mt = 0; mt < 4; mt++)
#pragma unroll
        for (int nt = 0; nt < 8; nt++)
#pragma unroll
            for (int q = 0; q < 4; q++) c[mt][nt][q] = 0.f;

    const int nk = Ksize / 64;

    // prologue: stages 0, 1
#pragma unroll
    for (int s = 0; s < 2; s++) {
        uint32_t sb = sm + (uint32_t)s * STAGE_BYTES;
#pragma unroll
        for (int i = 0; i < 8; i++)
            cp16(sb + aD0 + (uint32_t)i * 2048u, Ab + arow[i] + s * 64);
#pragma unroll
        for (int i = 0; i < 8; i++)
            cp16(sb + SM_A_BYTES + bD0 + (uint32_t)i * (4u * SM_B_STRIDE),
                 Brow + (size_t)(s * 32 + 4 * i) * N);
        cp_commit();
    }

    int stage = 0;
    for (int kc = 0; kc < nk; kc++) {
        cp_wait1();
        __syncthreads();
        if (kc + 2 < nk) {
            int s2 = stage + 2; if (s2 >= NSTAGE) s2 -= NSTAGE;
            uint32_t sb = sm + (uint32_t)s2 * STAGE_BYTES;
            int ko = (kc + 2) * 64;
#pragma unroll
            for (int i = 0; i < 8; i++)
                cp16(sb + aD0 + (uint32_t)i * 2048u, Ab + arow[i] + ko);
#pragma unroll
            for (int i = 0; i < 8; i++)
                cp16(sb + SM_A_BYTES + bD0 + (uint32_t)i * (4u * SM_B_STRIDE),
                     Brow + (size_t)((kc + 2) * 32 + 4 * i) * N);
        }
        cp_commit();

        uint32_t aB = sm + (uint32_t)stage * STAGE_BYTES;
        uint32_t bB = aB + SM_A_BYTES;
#pragma unroll
        for (int ks = 0; ks < 4; ks++) {
            uint32_t af[4][4];
#pragma unroll
            for (int mt = 0; mt < 4; mt++)
                ldm4(aB + aRelL + (uint32_t)(mt * 2048) + uoffL[ks], af[mt]);
            uint32_t bf[8][2];
#pragma unroll
            for (int nt = 0; nt < 8; nt++) {
                uint32_t b0 = bB + brel[nt] + (uint32_t)(ks * 8 * SM_B_STRIDE);
                bf[nt][0] = ldsu(b0);
                bf[nt][1] = ldsu(b0 + 4u * SM_B_STRIDE);
            }
#pragma unroll
            for (int mt = 0; mt < 4; mt++)
#pragma unroll
                for (int nt = 0; nt < 8; nt++)
                    mma_f16(c[mt][nt], af[mt], bf[nt]);
        }
        stage++; if (stage >= NSTAGE) stage -= NSTAGE;
    }

    // ---- epilogue ----
#pragma unroll
    for (int mt = 0; mt < 4; mt++) {
#pragma unroll
        for (int half = 0; half < 2; half++) {
            int r = wm * 64 + mt * 16 + gid + half * 8;
            if (r < mc) {
#pragma unroll
                for (int nt = 0; nt < 8; nt++) {
                    int nc = n0 + wn * 64 + nt * 8 + 2 * tig;
                    float v0 = c[mt][nt][half * 2 + 0] + biasE[nc];
                    float v1 = c[mt][nt][half * 2 + 1] + biasE[nc + 1];
                    if (RELU) {
                        v0 = fmaxf(v0, 0.f); v1 = fmaxf(v1, 0.f);
                        unsigned* orow = reinterpret_cast<unsigned*>(
                            g_hh + (size_t)(slot0 + r) * N);
                        orow[nc / 2] = pack2(v0, v1);
                    } else {
                        float* orow = g_y + (size_t)(slot0 + r) * N;
                        orow[nc]     = v0;
                        orow[nc + 1] = v1;
                    }
                }
            }
        }
    }
}

// ---------------- combine ----------------
__global__ void combine_kernel(float* __restrict__ out) {
    int idx = blockIdx.x * blockDim.x + threadIdx.x;
    if (idx >= T_TOK * (DMODEL / 4)) return;
    int t = idx / (DMODEL / 4);
    int j = (idx % (DMODEL / 4)) * 4;
    float w0 = g_w0[t], w1 = g_w1w[t];
    const float4 a = *reinterpret_cast<const float4*>(&g_y[(size_t)g_s0[t] * DMODEL + j]);
    const float4 b = *reinterpret_cast<const float4*>(&g_y[(size_t)g_s1[t] * DMODEL + j]);
    float4 o;
    o.x = w0 * a.x + w1 * b.x;
    o.y = w0 * a.y + w1 * b.y;
    o.z = w0 * a.z + w1 * b.z;
    o.w = w0 * a.w + w1 * b.w;
    *reinterpret_cast<float4*>(out + (size_t)t * DMODEL + j) = o;
}

// ---------------- launch (index 3 = GEMM1 for ncu) ----------------
extern "C" void kernel_launch(void* const* d_in, const int* in_sizes, int n_in,
                              void* d_out, int out_size) {
    const float* x      = (const float*)d_in[0];
    const float* gumbel = (const float*)d_in[1];
    const float* gw     = (const float*)d_in[2];
    const float* gb     = (const float*)d_in[3];
    const float* w1     = (const float*)d_in[4];
    const float* b1     = (const float*)d_in[5];
    const float* w2     = (const float*)d_in[6];
    const float* b2     = (const float*)d_in[7];
    float* out = (float*)d_out;

    cudaFuncSetAttribute(gemm_fp16<true, true>,
                         cudaFuncAttributeMaxDynamicSharedMemorySize, SMEM_TOT);
    cudaFuncSetAttribute(gemm_fp16<false, false>,
                         cudaFuncAttributeMaxDynamicSharedMemorySize, SMEM_TOT);

    __half* xh;  cudaGetSymbolAddress((void**)&xh,  g_xh);
    unsigned* w1h; cudaGetSymbolAddress((void**)&w1h, g_w1h);
    unsigned* w2h; cudaGetSymbolAddress((void**)&w2h, g_w2h);

    // 0: weight conversion to packed half2 (+ counter zeroing)
    size_t nU = 2 * W_UINTS;
    convert_w<<<(unsigned)((nU + 255) / 256), 256>>>(w1, w2);
    // 1: gate
    gate_kernel<<<T_TOK * 32 / 256, 256>>>(x, gumbel, gw, gb);
    // 2: tile map
    tilemap_kernel<<<1, 32>>>();
    // 3: GEMM1  h = fp16(relu(xh[tok] @ w1[e] + b1[e]))   K=DMODEL, N=DFF
    gemm_fp16<true, true><<<dim3(DFF / 128, MAXTILES), 128, SMEM_TOT>>>(
        xh, DMODEL, w1h, (long)(DMODEL / 2) * DFF, DFF, b1, DMODEL);
    // 4: GEMM2  y = hh @ w2[e] + b2[e]                    K=DFF, N=DMODEL
    gemm_fp16<false, false><<<dim3(DMODEL / 128, MAXTILES), 128, SMEM_TOT>>>(
        nullptr, DFF, w2h, (long)(DFF / 2) * DMODEL, DMODEL, b2, DFF);
    // 5: combine
    combine_kernel<<<(T_TOK * (DMODEL / 4) + 255) / 256, 256>>>(out);
}